// round 1
// baseline (speedup 1.0000x reference)
#include <cuda_runtime.h>
#include <cuda_bf16.h>
#include <math.h>

// Problem constants
#define BATCH 2
#define SEQ   2048
#define HID   3584
#define NH    28
#define NKV   4
#define HD    128
#define GROUPS (NH / NKV)   // 7
#define MROWS (BATCH * SEQ) // 4096

// Scratch buffers (static device globals; no runtime allocation)
__device__ float g_q[MROWS * NH * HD];    // 4096 x 3584
__device__ float g_k[MROWS * NKV * HD];   // 4096 x 512
__device__ float g_v[MROWS * NKV * HD];   // 4096 x 512
__device__ float g_att[MROWS * NH * HD];  // 4096 x 3584

// ---------------------------------------------------------------------------
// GEMM: C[M,N] = A[M,K] @ B[N,K]^T (+ bias[n]); both A and B are K-major.
// 128x128 block tile, BK=16, 256 threads, 8x8 per-thread microtile.
// All dims divisible by tile sizes for this problem (no bounds checks).
// ---------------------------------------------------------------------------
#define BM 128
#define BN 128
#define BK 16

__global__ void __launch_bounds__(256) gemm_nt_bias(
    const float* __restrict__ A, const float* __restrict__ B,
    const float* __restrict__ bias, float* __restrict__ C,
    int M, int N, int K)
{
    __shared__ float As[BK][BM];
    __shared__ float Bs[BK][BN];

    const int tid = threadIdx.x;
    const int bm = blockIdx.y * BM;
    const int bn = blockIdx.x * BN;
    const int tx = tid & 15;        // n-dim
    const int ty = tid >> 4;        // m-dim
    const int lrow = tid >> 2;      // 0..63
    const int lcol = (tid & 3) << 2; // 0,4,8,12

    float acc[8][8];
#pragma unroll
    for (int i = 0; i < 8; i++)
#pragma unroll
        for (int j = 0; j < 8; j++) acc[i][j] = 0.f;

    const float* Aptr = A + (size_t)(bm + lrow) * K + lcol;
    const float* Bptr = B + (size_t)(bn + lrow) * K + lcol;

    for (int k0 = 0; k0 < K; k0 += BK) {
#pragma unroll
        for (int i = 0; i < 2; i++) {
            int r = lrow + i * 64;
            float4 va = *(const float4*)(Aptr + (size_t)(i * 64) * K + k0);
            As[lcol + 0][r] = va.x; As[lcol + 1][r] = va.y;
            As[lcol + 2][r] = va.z; As[lcol + 3][r] = va.w;
            float4 vb = *(const float4*)(Bptr + (size_t)(i * 64) * K + k0);
            Bs[lcol + 0][r] = vb.x; Bs[lcol + 1][r] = vb.y;
            Bs[lcol + 2][r] = vb.z; Bs[lcol + 3][r] = vb.w;
        }
        __syncthreads();

#pragma unroll
        for (int k = 0; k < BK; k++) {
            float a[8], b[8];
            *(float4*)&a[0] = *(float4*)&As[k][ty * 8];
            *(float4*)&a[4] = *(float4*)&As[k][ty * 8 + 4];
            *(float4*)&b[0] = *(float4*)&Bs[k][tx * 8];
            *(float4*)&b[4] = *(float4*)&Bs[k][tx * 8 + 4];
#pragma unroll
            for (int i = 0; i < 8; i++)
#pragma unroll
                for (int j = 0; j < 8; j++)
                    acc[i][j] = fmaf(a[i], b[j], acc[i][j]);
        }
        __syncthreads();
    }

    float bv_[8];
#pragma unroll
    for (int j = 0; j < 8; j++)
        bv_[j] = bias ? bias[bn + tx * 8 + j] : 0.f;

#pragma unroll
    for (int i = 0; i < 8; i++) {
        int m = bm + ty * 8 + i;
#pragma unroll
        for (int j = 0; j < 8; j += 4) {
            int n = bn + tx * 8 + j;
            float4 v;
            v.x = acc[i][j + 0] + bv_[j + 0];
            v.y = acc[i][j + 1] + bv_[j + 1];
            v.z = acc[i][j + 2] + bv_[j + 2];
            v.w = acc[i][j + 3] + bv_[j + 3];
            *(float4*)&C[(size_t)m * N + n] = v;
        }
    }
}

// ---------------------------------------------------------------------------
// RoPE: in-place on x[M, nheads*128].
// out[d]    = x[d]*cos[d]    - x[d+64]*sin[d]      (d < 64)
// out[d+64] = x[d+64]*cos[d+64] + x[d]*sin[d+64]
// One thread handles the (d, d+64) pair.
// ---------------------------------------------------------------------------
__global__ void rope_kernel(float* __restrict__ x,
                            const float* __restrict__ cosp,
                            const float* __restrict__ sinp,
                            int nheads)
{
    int idx = blockIdx.x * blockDim.x + threadIdx.x;
    int total = MROWS * nheads * 64;
    if (idx >= total) return;
    int d = idx & 63;
    int t = idx >> 6;
    int hd = t % nheads;
    int row = t / nheads;

    float* p = x + (size_t)row * nheads * HD + hd * HD;
    const float* cr = cosp + (size_t)row * HD;
    const float* sr = sinp + (size_t)row * HD;

    float x1 = p[d], x2 = p[d + 64];
    float c1 = cr[d], c2 = cr[d + 64];
    float s1 = sr[d], s2 = sr[d + 64];
    p[d]      = x1 * c1 - x2 * s1;
    p[d + 64] = x2 * c2 + x1 * s2;
}

// ---------------------------------------------------------------------------
// Causal GQA flash attention (fp32 SIMT, online softmax).
// Block: 256 threads handling 64 query rows; 4 lanes per q-row, each lane
// owns 32 of the 128 d-columns. KV tiles of 32 keys staged in SMEM.
// Grid: (SEQ/64, NH, BATCH).
// ---------------------------------------------------------------------------
#define AQ 64
#define AK 32

__global__ void __launch_bounds__(256) attn_kernel(
    const float* __restrict__ Q, const float* __restrict__ Kg,
    const float* __restrict__ Vg, float* __restrict__ O)
{
    __shared__ float Ks[AK][HD];
    __shared__ float Vs[AK][HD];

    const int tid = threadIdx.x;
    const int qi = tid >> 2;
    const int l4 = tid & 3;
    const int q0 = blockIdx.x * AQ;
    const int h  = blockIdx.y;
    const int b  = blockIdx.z;
    const int kvh = h / GROUPS;
    const int qg = q0 + qi;
    const float scale = 0.08838834764831845f; // 1/sqrt(128)

    float qreg[32];
    {
        const float* qp = Q + ((size_t)(b * SEQ + qg)) * (NH * HD) + h * HD + l4 * 32;
#pragma unroll
        for (int j = 0; j < 32; j += 4) {
            float4 t = *(const float4*)(qp + j);
            qreg[j + 0] = t.x * scale; qreg[j + 1] = t.y * scale;
            qreg[j + 2] = t.z * scale; qreg[j + 3] = t.w * scale;
        }
    }

    float acc[32];
#pragma unroll
    for (int j = 0; j < 32; j++) acc[j] = 0.f;
    float m = -1e30f, l = 0.f;

    const int nk = q0 + AQ;
    for (int kt = 0; kt < nk; kt += AK) {
        // stage K/V tiles: 4096 floats each = 1024 float4, 4 per thread
#pragma unroll
        for (int i = 0; i < 4; i++) {
            int fi = tid + i * 256;
            int r = fi >> 5;
            int c = (fi & 31) << 2;
            size_t gidx = ((size_t)(b * SEQ + kt + r)) * (NKV * HD) + kvh * HD + c;
            *(float4*)&Ks[r][c] = *(const float4*)&Kg[gidx];
            *(float4*)&Vs[r][c] = *(const float4*)&Vg[gidx];
        }
        __syncthreads();

#pragma unroll
        for (int cch = 0; cch < 2; cch++) {
            float s[16];
#pragma unroll
            for (int kk = 0; kk < 16; kk++) {
                int kr = cch * 16 + kk;
                const float* kp = &Ks[kr][l4 * 32];
                float p = 0.f;
#pragma unroll
                for (int j = 0; j < 32; j++) p = fmaf(qreg[j], kp[j], p);
                p += __shfl_xor_sync(0xffffffffu, p, 1);
                p += __shfl_xor_sync(0xffffffffu, p, 2);
                s[kk] = (kt + kr <= qg) ? p : -1e30f;
            }
            float mx = m;
#pragma unroll
            for (int kk = 0; kk < 16; kk++) mx = fmaxf(mx, s[kk]);
            float corr = __expf(m - mx);
            m = mx;
            l *= corr;
#pragma unroll
            for (int j = 0; j < 32; j++) acc[j] *= corr;
#pragma unroll
            for (int kk = 0; kk < 16; kk++) {
                float p = __expf(s[kk] - mx);
                l += p;
                const float* vp = &Vs[cch * 16 + kk][l4 * 32];
#pragma unroll
                for (int j = 0; j < 32; j++) acc[j] = fmaf(p, vp[j], acc[j]);
            }
        }
        __syncthreads();
    }

    float inv = 1.f / l;
    float* op = O + ((size_t)(b * SEQ + qg)) * (NH * HD) + h * HD + l4 * 32;
#pragma unroll
    for (int j = 0; j < 32; j += 4) {
        float4 v;
        v.x = acc[j + 0] * inv; v.y = acc[j + 1] * inv;
        v.z = acc[j + 2] * inv; v.w = acc[j + 3] * inv;
        *(float4*)(op + j) = v;
    }
}

// ---------------------------------------------------------------------------
// Host launcher
// ---------------------------------------------------------------------------
extern "C" void kernel_launch(void* const* d_in, const int* in_sizes, int n_in,
                              void* d_out, int out_size)
{
    const float* hs   = (const float*)d_in[0]; // [B,S,HID]
    const float* cosp = (const float*)d_in[1]; // [B,S,D]
    const float* sinp = (const float*)d_in[2]; // [B,S,D]
    const float* Wq   = (const float*)d_in[3]; // [NH*D, HID]
    const float* bq   = (const float*)d_in[4];
    const float* Wk   = (const float*)d_in[5]; // [NKV*D, HID]
    const float* bk   = (const float*)d_in[6];
    const float* Wv   = (const float*)d_in[7];
    const float* bv   = (const float*)d_in[8];
    const float* Wo   = (const float*)d_in[9]; // [HID, NH*D]
    float* out = (float*)d_out;

    float *qp, *kp, *vp, *ap;
    cudaGetSymbolAddress((void**)&qp, g_q);
    cudaGetSymbolAddress((void**)&kp, g_k);
    cudaGetSymbolAddress((void**)&vp, g_v);
    cudaGetSymbolAddress((void**)&ap, g_att);

    // QKV projections
    gemm_nt_bias<<<dim3(NH * HD / BN, MROWS / BM), 256>>>(hs, Wq, bq, qp, MROWS, NH * HD, HID);
    gemm_nt_bias<<<dim3(NKV * HD / BN, MROWS / BM), 256>>>(hs, Wk, bk, kp, MROWS, NKV * HD, HID);
    gemm_nt_bias<<<dim3(NKV * HD / BN, MROWS / BM), 256>>>(hs, Wv, bv, vp, MROWS, NKV * HD, HID);

    // RoPE on Q and K
    rope_kernel<<<(MROWS * NH * 64 + 255) / 256, 256>>>(qp, cosp, sinp, NH);
    rope_kernel<<<(MROWS * NKV * 64 + 255) / 256, 256>>>(kp, cosp, sinp, NKV);

    // Causal GQA attention
    attn_kernel<<<dim3(SEQ / AQ, NH, BATCH), 256>>>(qp, kp, vp, ap);

    // Output projection
    gemm_nt_bias<<<dim3(HID / BN, MROWS / BM), 256>>>(ap, Wo, nullptr, out, MROWS, HID, HID);
}

// round 3
// speedup vs baseline: 1.2158x; 1.2158x over previous
#include <cuda_runtime.h>
#include <cuda_bf16.h>
#include <math.h>
#include <stdint.h>

// Problem constants
#define BATCH 2
#define SEQ   2048
#define HID   3584
#define NH    28
#define NKV   4
#define HD    128
#define GROUPS (NH / NKV)   // 7
#define MROWS (BATCH * SEQ) // 4096

// Scratch buffers (static device globals; no runtime allocation)
__device__ float g_q[MROWS * NH * HD];    // 4096 x 3584
__device__ float g_k[MROWS * NKV * HD];   // 4096 x 512
__device__ float g_v[MROWS * NKV * HD];   // 4096 x 512
__device__ float g_att[MROWS * NH * HD];  // 4096 x 3584

// ---------------------------------------------------------------------------
// TF32 tensor-core GEMM: C[M,N] = A[M,K] @ B[N,K]^T (+ bias[n]).
// A and B both K-major (row-major [rows,K]). 128x128 CTA tile, BK=16,
// 256 threads = 8 warps, each warp 64(m) x 32(n) via m16n8k8 mma.sync.
// Dims assumed divisible by tiles (true for this problem).
// ---------------------------------------------------------------------------
#define BM 128
#define BN 128
#define BKS 16
#define SKP 20   // padded smem row stride (16 + 4)

__device__ __forceinline__ uint32_t f2tf32(float x) {
    uint32_t r;
    asm("cvt.rna.tf32.f32 %0, %1;" : "=r"(r) : "f"(x));
    return r;
}

__device__ __forceinline__ void mma_tf32(float* c, const uint32_t* a, const uint32_t* b) {
    asm volatile(
        "mma.sync.aligned.m16n8k8.row.col.f32.tf32.tf32.f32 "
        "{%0,%1,%2,%3}, {%4,%5,%6,%7}, {%8,%9}, {%0,%1,%2,%3};"
        : "+f"(c[0]), "+f"(c[1]), "+f"(c[2]), "+f"(c[3])
        : "r"(a[0]), "r"(a[1]), "r"(a[2]), "r"(a[3]), "r"(b[0]), "r"(b[1]));
}

__global__ void __launch_bounds__(256, 2) gemm_tf32(
    const float* __restrict__ A, const float* __restrict__ B,
    const float* __restrict__ bias, float* __restrict__ C,
    int M, int N, int K)
{
    __shared__ uint32_t As[BM][SKP];
    __shared__ uint32_t Bs[BN][SKP];

    const int tid  = threadIdx.x;
    const int lane = tid & 31;
    const int warp = tid >> 5;
    const int wm   = warp & 1;    // 0..1 -> m offset 0/64
    const int wn   = warp >> 1;   // 0..3 -> n offset 0/32/64/96

    const int bm = blockIdx.y * BM;
    const int bn = blockIdx.x * BN;

    const int srow = tid >> 2;        // 0..63
    const int scg  = (tid & 3) << 2;  // 0,4,8,12

    float acc[4][4][4];
#pragma unroll
    for (int mi = 0; mi < 4; mi++)
#pragma unroll
        for (int ni = 0; ni < 4; ni++)
#pragma unroll
            for (int r = 0; r < 4; r++) acc[mi][ni][r] = 0.f;

    const float* Ap = A + (size_t)(bm + srow) * K + scg;
    const float* Bp = B + (size_t)(bn + srow) * K + scg;

    // prefetch first tile to registers
    float4 pa[2], pb[2];
#pragma unroll
    for (int i = 0; i < 2; i++) {
        pa[i] = *(const float4*)(Ap + (size_t)(i * 64) * K);
        pb[i] = *(const float4*)(Bp + (size_t)(i * 64) * K);
    }

    for (int k0 = 0; k0 < K; k0 += BKS) {
        // store staged registers to smem (with tf32 rounding)
#pragma unroll
        for (int i = 0; i < 2; i++) {
            int r = srow + i * 64;
            As[r][scg + 0] = f2tf32(pa[i].x); As[r][scg + 1] = f2tf32(pa[i].y);
            As[r][scg + 2] = f2tf32(pa[i].z); As[r][scg + 3] = f2tf32(pa[i].w);
            Bs[r][scg + 0] = f2tf32(pb[i].x); Bs[r][scg + 1] = f2tf32(pb[i].y);
            Bs[r][scg + 2] = f2tf32(pb[i].z); Bs[r][scg + 3] = f2tf32(pb[i].w);
        }
        __syncthreads();

        // prefetch next tile while computing this one
        if (k0 + BKS < K) {
#pragma unroll
            for (int i = 0; i < 2; i++) {
                pa[i] = *(const float4*)(Ap + (size_t)(i * 64) * K + k0 + BKS);
                pb[i] = *(const float4*)(Bp + (size_t)(i * 64) * K + k0 + BKS);
            }
        }

#pragma unroll
        for (int ks = 0; ks < 2; ks++) {
            const int kc = ks * 8 + (lane & 3);
            uint32_t af[4][4];
#pragma unroll
            for (int mi = 0; mi < 4; mi++) {
                int r = wm * 64 + mi * 16 + (lane >> 2);
                af[mi][0] = As[r][kc];
                af[mi][1] = As[r + 8][kc];
                af[mi][2] = As[r][kc + 4];
                af[mi][3] = As[r + 8][kc + 4];
            }
            uint32_t bf[4][2];
#pragma unroll
            for (int ni = 0; ni < 4; ni++) {
                int n = wn * 32 + ni * 8 + (lane >> 2);
                bf[ni][0] = Bs[n][kc];
                bf[ni][1] = Bs[n][kc + 4];
            }
#pragma unroll
            for (int mi = 0; mi < 4; mi++)
#pragma unroll
                for (int ni = 0; ni < 4; ni++)
                    mma_tf32(acc[mi][ni], af[mi], bf[ni]);
        }
        __syncthreads();
    }

    // epilogue: c0,c1 -> (row, col..col+1); c2,c3 -> (row+8, col..col+1)
#pragma unroll
    for (int mi = 0; mi < 4; mi++) {
        int r = bm + wm * 64 + mi * 16 + (lane >> 2);
#pragma unroll
        for (int ni = 0; ni < 4; ni++) {
            int c = bn + wn * 32 + ni * 8 + (lane & 3) * 2;
            float b0 = bias ? bias[c]     : 0.f;
            float b1 = bias ? bias[c + 1] : 0.f;
            float2 v0 = make_float2(acc[mi][ni][0] + b0, acc[mi][ni][1] + b1);
            float2 v1 = make_float2(acc[mi][ni][2] + b0, acc[mi][ni][3] + b1);
            *(float2*)&C[(size_t)r * N + c]       = v0;
            *(float2*)&C[(size_t)(r + 8) * N + c] = v1;
        }
    }
}

// ---------------------------------------------------------------------------
// RoPE: in-place on x[M, nheads*128].
// ---------------------------------------------------------------------------
__global__ void rope_kernel(float* __restrict__ x,
                            const float* __restrict__ cosp,
                            const float* __restrict__ sinp,
                            int nheads)
{
    int idx = blockIdx.x * blockDim.x + threadIdx.x;
    int total = MROWS * nheads * 64;
    if (idx >= total) return;
    int d = idx & 63;
    int t = idx >> 6;
    int hd = t % nheads;
    int row = t / nheads;

    float* p = x + (size_t)row * nheads * HD + hd * HD;
    const float* cr = cosp + (size_t)row * HD;
    const float* sr = sinp + (size_t)row * HD;

    float x1 = p[d], x2 = p[d + 64];
    float c1 = cr[d], c2 = cr[d + 64];
    float s1 = sr[d], s2 = sr[d + 64];
    p[d]      = x1 * c1 - x2 * s1;
    p[d + 64] = x2 * c2 + x1 * s2;
}

// ---------------------------------------------------------------------------
// Causal GQA flash attention (fp32 SIMT, online softmax).
// ---------------------------------------------------------------------------
#define AQ 64
#define AK 32

__global__ void __launch_bounds__(256) attn_kernel(
    const float* __restrict__ Q, const float* __restrict__ Kg,
    const float* __restrict__ Vg, float* __restrict__ O)
{
    __shared__ float Ks[AK][HD];
    __shared__ float Vs[AK][HD];

    const int tid = threadIdx.x;
    const int qi = tid >> 2;
    const int l4 = tid & 3;
    const int q0 = blockIdx.x * AQ;
    const int h  = blockIdx.y;
    const int b  = blockIdx.z;
    const int kvh = h / GROUPS;
    const int qg = q0 + qi;
    const float scale = 0.08838834764831845f; // 1/sqrt(128)

    float qreg[32];
    {
        const float* qp = Q + ((size_t)(b * SEQ + qg)) * (NH * HD) + h * HD + l4 * 32;
#pragma unroll
        for (int j = 0; j < 32; j += 4) {
            float4 t = *(const float4*)(qp + j);
            qreg[j + 0] = t.x * scale; qreg[j + 1] = t.y * scale;
            qreg[j + 2] = t.z * scale; qreg[j + 3] = t.w * scale;
        }
    }

    float acc[32];
#pragma unroll
    for (int j = 0; j < 32; j++) acc[j] = 0.f;
    float m = -1e30f, l = 0.f;

    const int nk = q0 + AQ;
    for (int kt = 0; kt < nk; kt += AK) {
#pragma unroll
        for (int i = 0; i < 4; i++) {
            int fi = tid + i * 256;
            int r = fi >> 5;
            int c = (fi & 31) << 2;
            size_t gidx = ((size_t)(b * SEQ + kt + r)) * (NKV * HD) + kvh * HD + c;
            *(float4*)&Ks[r][c] = *(const float4*)&Kg[gidx];
            *(float4*)&Vs[r][c] = *(const float4*)&Vg[gidx];
        }
        __syncthreads();

#pragma unroll
        for (int cch = 0; cch < 2; cch++) {
            float s[16];
#pragma unroll
            for (int kk = 0; kk < 16; kk++) {
                int kr = cch * 16 + kk;
                const float* kp = &Ks[kr][l4 * 32];
                float p = 0.f;
#pragma unroll
                for (int j = 0; j < 32; j++) p = fmaf(qreg[j], kp[j], p);
                p += __shfl_xor_sync(0xffffffffu, p, 1);
                p += __shfl_xor_sync(0xffffffffu, p, 2);
                s[kk] = (kt + kr <= qg) ? p : -1e30f;
            }
            float mx = m;
#pragma unroll
            for (int kk = 0; kk < 16; kk++) mx = fmaxf(mx, s[kk]);
            float corr = __expf(m - mx);
            m = mx;
            l *= corr;
#pragma unroll
            for (int j = 0; j < 32; j++) acc[j] *= corr;
#pragma unroll
            for (int kk = 0; kk < 16; kk++) {
                float p = __expf(s[kk] - mx);
                l += p;
                const float* vp = &Vs[cch * 16 + kk][l4 * 32];
#pragma unroll
                for (int j = 0; j < 32; j++) acc[j] = fmaf(p, vp[j], acc[j]);
            }
        }
        __syncthreads();
    }

    float inv = 1.f / l;
    float* op = O + ((size_t)(b * SEQ + qg)) * (NH * HD) + h * HD + l4 * 32;
#pragma unroll
    for (int j = 0; j < 32; j += 4) {
        float4 v;
        v.x = acc[j + 0] * inv; v.y = acc[j + 1] * inv;
        v.z = acc[j + 2] * inv; v.w = acc[j + 3] * inv;
        *(float4*)(op + j) = v;
    }
}

// ---------------------------------------------------------------------------
// Host launcher
// ---------------------------------------------------------------------------
extern "C" void kernel_launch(void* const* d_in, const int* in_sizes, int n_in,
                              void* d_out, int out_size)
{
    const float* hs   = (const float*)d_in[0]; // [B,S,HID]
    const float* cosp = (const float*)d_in[1]; // [B,S,D]
    const float* sinp = (const float*)d_in[2]; // [B,S,D]
    const float* Wq   = (const float*)d_in[3]; // [NH*D, HID]
    const float* bq   = (const float*)d_in[4];
    const float* Wk   = (const float*)d_in[5]; // [NKV*D, HID]
    const float* bk   = (const float*)d_in[6];
    const float* Wv   = (const float*)d_in[7];
    const float* bv   = (const float*)d_in[8];
    const float* Wo   = (const float*)d_in[9]; // [HID, NH*D]
    float* out = (float*)d_out;

    float *qp, *kp, *vp, *ap;
    cudaGetSymbolAddress((void**)&qp, g_q);
    cudaGetSymbolAddress((void**)&kp, g_k);
    cudaGetSymbolAddress((void**)&vp, g_v);
    cudaGetSymbolAddress((void**)&ap, g_att);

    // QKV projections (TF32 tensor cores)
    gemm_tf32<<<dim3(NH * HD / BN, MROWS / BM), 256>>>(hs, Wq, bq, qp, MROWS, NH * HD, HID);
    gemm_tf32<<<dim3(NKV * HD / BN, MROWS / BM), 256>>>(hs, Wk, bk, kp, MROWS, NKV * HD, HID);
    gemm_tf32<<<dim3(NKV * HD / BN, MROWS / BM), 256>>>(hs, Wv, bv, vp, MROWS, NKV * HD, HID);

    // RoPE on Q and K
    rope_kernel<<<(MROWS * NH * 64 + 255) / 256, 256>>>(qp, cosp, sinp, NH);
    rope_kernel<<<(MROWS * NKV * 64 + 255) / 256, 256>>>(kp, cosp, sinp, NKV);

    // Causal GQA attention
    attn_kernel<<<dim3(SEQ / AQ, NH, BATCH), 256>>>(qp, kp, vp, ap);

    // Output projection (TF32 tensor cores)
    gemm_tf32<<<dim3(HID / BN, MROWS / BM), 256>>>(ap, Wo, nullptr, out, MROWS, HID, HID);
}

// round 7
// speedup vs baseline: 2.9782x; 2.4495x over previous
#include <cuda_runtime.h>
#include <cuda_bf16.h>
#include <math.h>
#include <stdint.h>

// Problem constants
#define BATCH 2
#define SEQ   2048
#define HID   3584
#define NH    28
#define NKV   4
#define HD    128
#define GROUPS (NH / NKV)   // 7
#define MROWS (BATCH * SEQ) // 4096

// Scratch buffers (static device globals; no runtime allocation)
__device__ float    g_q[MROWS * NH * HD];     // fp32 Q after proj+rope
__device__ float    g_k[MROWS * NKV * HD];    // fp32 K after proj+rope
__device__ float    g_v[MROWS * NKV * HD];    // fp32 V
__device__ uint32_t g_att[MROWS * NH * HD];   // attn out, tf32 bits
__device__ uint32_t g_hs_t[MROWS * HID];      // hidden_states, tf32 bits
__device__ uint32_t g_wq_t[NH * HD * HID];
__device__ uint32_t g_wk_t[NKV * HD * HID];
__device__ uint32_t g_wv_t[NKV * HD * HID];
__device__ uint32_t g_wo_t[HID * NH * HD];

// ---------------------------------------------------------------------------
// Helpers
// ---------------------------------------------------------------------------
__device__ __forceinline__ uint32_t f2tf32(float x) {
    uint32_t r;
    asm("cvt.rna.tf32.f32 %0, %1;" : "=r"(r) : "f"(x));
    return r;
}

__device__ __forceinline__ void mma_tf32(float* c, const uint32_t* a, const uint32_t* b) {
    asm volatile(
        "mma.sync.aligned.m16n8k8.row.col.f32.tf32.tf32.f32 "
        "{%0,%1,%2,%3}, {%4,%5,%6,%7}, {%8,%9}, {%0,%1,%2,%3};"
        : "+f"(c[0]), "+f"(c[1]), "+f"(c[2]), "+f"(c[3])
        : "r"(a[0]), "r"(a[1]), "r"(a[2]), "r"(a[3]), "r"(b[0]), "r"(b[1]));
}

__device__ __forceinline__ uint32_t smem_u32(const void* p) {
    return (uint32_t)__cvta_generic_to_shared(p);
}
__device__ __forceinline__ void cp_async16(uint32_t dst, const void* src) {
    asm volatile("cp.async.cg.shared.global [%0], [%1], 16;\n" :: "r"(dst), "l"(src));
}
#define CP_COMMIT() asm volatile("cp.async.commit_group;\n")
#define CP_WAIT1()  asm volatile("cp.async.wait_group 1;\n")

// ---------------------------------------------------------------------------
// Elementwise fp32 -> tf32-rounded-bits pre-pass (n divisible by 4)
// ---------------------------------------------------------------------------
__global__ void cvt_tf32_kernel(const float* __restrict__ src,
                                uint32_t* __restrict__ dst, int n)
{
    int i = (blockIdx.x * blockDim.x + threadIdx.x) * 4;
    if (i >= n) return;
    float4 v = *(const float4*)(src + i);
    uint4 o;
    o.x = f2tf32(v.x); o.y = f2tf32(v.y); o.z = f2tf32(v.z); o.w = f2tf32(v.w);
    *(uint4*)(dst + i) = o;
}

// ---------------------------------------------------------------------------
// TF32 GEMM v2: C[M,N] = A[M,K] @ B[N,K]^T (+bias). A,B are tf32 bits.
// 128x128 CTA, BK=16, 3-stage cp.async, 4 warps each 64x64 (m16n8k8 mma).
// ---------------------------------------------------------------------------
#define GSKP 20                      // smem word stride per row
#define GSTAGE_WORDS (128 * GSKP)    // 2560 words per operand per stage
#define GEMM_SMEM (3 * 2 * GSTAGE_WORDS * 4)  // 61440 bytes

__global__ void __launch_bounds__(128) gemm_tf32_v2(
    const uint32_t* __restrict__ A, const uint32_t* __restrict__ B,
    const float* __restrict__ bias, float* __restrict__ C,
    int M, int N, int K)
{
    extern __shared__ unsigned char dynsmem[];
    uint32_t* Asb = (uint32_t*)dynsmem;                   // [3][128][20]
    uint32_t* Bsb = Asb + 3 * GSTAGE_WORDS;               // [3][128][20]

    const int tid  = threadIdx.x;
    const int lane = tid & 31;
    const int warp = tid >> 5;
    const int wm   = warp & 1;   // m offset 0/64
    const int wn   = warp >> 1;  // n offset 0/64
    const int bm = blockIdx.y * 128;
    const int bn = blockIdx.x * 128;

    const uint32_t* Ap = A + (size_t)(bm + tid) * K;
    const uint32_t* Bp = B + (size_t)(bn + tid) * K;
    const uint32_t sA = smem_u32(Asb + tid * GSKP);
    const uint32_t sB = smem_u32(Bsb + tid * GSKP);

    float acc[4][8][4];
#pragma unroll
    for (int mi = 0; mi < 4; mi++)
#pragma unroll
        for (int ni = 0; ni < 8; ni++)
#pragma unroll
            for (int r = 0; r < 4; r++) acc[mi][ni][r] = 0.f;

    const int ktiles = K / 16;

    // stage loader: 4x16B for A row, 4x16B for B row
#define LOAD_STAGE(s, k0) do {                                         \
        uint32_t da = sA + (s) * (GSTAGE_WORDS * 4);                   \
        uint32_t db = sB + (s) * (GSTAGE_WORDS * 4);                   \
        _Pragma("unroll")                                              \
        for (int c = 0; c < 4; c++) {                                  \
            cp_async16(da + c * 16, Ap + (k0) + c * 4);                \
            cp_async16(db + c * 16, Bp + (k0) + c * 4);                \
        }                                                              \
    } while (0)

    LOAD_STAGE(0, 0);  CP_COMMIT();
    LOAD_STAGE(1, 16); CP_COMMIT();

    int s_load = 2;   // next stage slot to fill
    int s_cur  = 0;   // stage being computed
    for (int t = 0; t < ktiles; t++) {
        CP_WAIT1();
        __syncthreads();
        if (t + 2 < ktiles) LOAD_STAGE(s_load, (t + 2) * 16);
        CP_COMMIT();
        if (++s_load == 3) s_load = 0;

        const uint32_t* As_ = Asb + s_cur * GSTAGE_WORDS;
        const uint32_t* Bs_ = Bsb + s_cur * GSTAGE_WORDS;
        if (++s_cur == 3) s_cur = 0;

#pragma unroll
        for (int ks = 0; ks < 2; ks++) {
            const int kc = ks * 8 + (lane & 3);
            uint32_t af[4][4];
#pragma unroll
            for (int mi = 0; mi < 4; mi++) {
                int r = wm * 64 + mi * 16 + (lane >> 2);
                af[mi][0] = As_[r * GSKP + kc];
                af[mi][1] = As_[(r + 8) * GSKP + kc];
                af[mi][2] = As_[r * GSKP + kc + 4];
                af[mi][3] = As_[(r + 8) * GSKP + kc + 4];
            }
            uint32_t bf[8][2];
#pragma unroll
            for (int ni = 0; ni < 8; ni++) {
                int n = wn * 64 + ni * 8 + (lane >> 2);
                bf[ni][0] = Bs_[n * GSKP + kc];
                bf[ni][1] = Bs_[n * GSKP + kc + 4];
            }
#pragma unroll
            for (int mi = 0; mi < 4; mi++)
#pragma unroll
                for (int ni = 0; ni < 8; ni++)
                    mma_tf32(acc[mi][ni], af[mi], bf[ni]);
        }
    }

    // epilogue
#pragma unroll
    for (int mi = 0; mi < 4; mi++) {
        int r = bm + wm * 64 + mi * 16 + (lane >> 2);
#pragma unroll
        for (int ni = 0; ni < 8; ni++) {
            int c = bn + wn * 64 + ni * 8 + (lane & 3) * 2;
            float b0 = bias ? bias[c]     : 0.f;
            float b1 = bias ? bias[c + 1] : 0.f;
            float2 v0 = make_float2(acc[mi][ni][0] + b0, acc[mi][ni][1] + b1);
            float2 v1 = make_float2(acc[mi][ni][2] + b0, acc[mi][ni][3] + b1);
            *(float2*)&C[(size_t)r * N + c]       = v0;
            *(float2*)&C[(size_t)(r + 8) * N + c] = v1;
        }
    }
#undef LOAD_STAGE
}

// ---------------------------------------------------------------------------
// RoPE: in-place on x[M, nheads*128].
// ---------------------------------------------------------------------------
__global__ void rope_kernel(float* __restrict__ x,
                            const float* __restrict__ cosp,
                            const float* __restrict__ sinp,
                            int nheads)
{
    int idx = blockIdx.x * blockDim.x + threadIdx.x;
    int total = MROWS * nheads * 64;
    if (idx >= total) return;
    int d = idx & 63;
    int t = idx >> 6;
    int hd = t % nheads;
    int row = t / nheads;

    float* p = x + (size_t)row * nheads * HD + hd * HD;
    const float* cr = cosp + (size_t)row * HD;
    const float* sr = sinp + (size_t)row * HD;

    float x1 = p[d], x2 = p[d + 64];
    float c1 = cr[d], c2 = cr[d + 64];
    float s1 = sr[d], s2 = sr[d + 64];
    p[d]      = x1 * c1 - x2 * s1;
    p[d + 64] = x2 * c2 + x1 * s2;
}

// ---------------------------------------------------------------------------
// Causal GQA flash attention v2 (fp32 math, online softmax).
// 512 threads, 128 q-rows/CTA, 4 lanes per q-row with block-rotated dim
// ownership (conflict-free 128-bit LDS). cp.async double-buffered K/V tiles
// of 32 keys. Output written as tf32 bits for the O-projection.
// ---------------------------------------------------------------------------
#define AQ2 128
#define AK2 32
#define AROW 132                        // padded floats per smem row
#define ATILE_WORDS (AK2 * AROW)        // 4224
#define ATTN_SMEM (4 * ATILE_WORDS * 4) // K[2] + V[2] = 67584 bytes

__global__ void __launch_bounds__(512) attn_kernel(
    const float* __restrict__ Q, const float* __restrict__ Kg,
    const float* __restrict__ Vg, uint32_t* __restrict__ O)
{
    extern __shared__ unsigned char dynsmem[];
    float* Ksb = (float*)dynsmem;                 // [2][32][132]
    float* Vsb = Ksb + 2 * ATILE_WORDS;           // [2][32][132]

    const int tid = threadIdx.x;
    const int qi  = tid >> 2;     // 0..127
    const int l4  = tid & 3;
    const int q0  = (gridDim.x - 1 - blockIdx.x) * AQ2;  // heavy blocks first
    const int h   = blockIdx.y;
    const int b   = blockIdx.z;
    const int kvh = h / GROUPS;
    const int qg  = q0 + qi;
    const float scale = 0.08838834764831845f; // 1/sqrt(128)

    // block-rotated dim ownership: thread owns dims l4*32 + ((bb+l4)&3)*8 + i
    int fbo[4];
#pragma unroll
    for (int bb = 0; bb < 4; bb++) fbo[bb] = l4 * 32 + (((bb + l4) & 3) * 8);

    // load Q (scaled) in rotated order
    float qreg[32];
    {
        const float* qp = Q + ((size_t)(b * SEQ + qg)) * (NH * HD) + h * HD;
#pragma unroll
        for (int bb = 0; bb < 4; bb++) {
            float4 t0 = *(const float4*)(qp + fbo[bb]);
            float4 t1 = *(const float4*)(qp + fbo[bb] + 4);
            qreg[bb * 8 + 0] = t0.x * scale; qreg[bb * 8 + 1] = t0.y * scale;
            qreg[bb * 8 + 2] = t0.z * scale; qreg[bb * 8 + 3] = t0.w * scale;
            qreg[bb * 8 + 4] = t1.x * scale; qreg[bb * 8 + 5] = t1.y * scale;
            qreg[bb * 8 + 6] = t1.z * scale; qreg[bb * 8 + 7] = t1.w * scale;
        }
    }

    float acc[32];
#pragma unroll
    for (int j = 0; j < 32; j++) acc[j] = 0.f;
    float m = -1e30f, l = 0.f;

    // cp.async staging: 1024 16B-chunks per operand per tile; 2 per thread
    const size_t kvrow = (size_t)(NKV * HD);
#define LOAD_TILE(st, kt) do {                                                  \
        _Pragma("unroll")                                                       \
        for (int cc = 0; cc < 2; cc++) {                                        \
            int ch  = tid + cc * 512;                                           \
            int r   = ch >> 5;                                                  \
            int col = (ch & 31) * 4;                                            \
            size_t g = ((size_t)(b * SEQ + (kt) + r)) * kvrow + kvh * HD + col; \
            cp_async16(smem_u32(Ksb + (st) * ATILE_WORDS + r * AROW + col),     \
                       Kg + g);                                                 \
            cp_async16(smem_u32(Vsb + (st) * ATILE_WORDS + r * AROW + col),     \
                       Vg + g);                                                 \
        }                                                                       \
    } while (0)

    const int ntiles = (q0 + AQ2) / AK2;
    LOAD_TILE(0, 0);
    CP_COMMIT();

    for (int t = 0; t < ntiles; t++) {
        if (t + 1 < ntiles) LOAD_TILE((t + 1) & 1, (t + 1) * AK2);
        CP_COMMIT();
        CP_WAIT1();
        __syncthreads();

        const float* kbase = Ksb + (t & 1) * ATILE_WORDS;
        const float* vbase = Vsb + (t & 1) * ATILE_WORDS;
        const int kt = t * AK2;
        const bool full = (kt + AK2 - 1 <= q0);

#pragma unroll
        for (int cch = 0; cch < 2; cch++) {
            float s[16];
#pragma unroll
            for (int kk = 0; kk < 16; kk++) {
                const int kr = cch * 16 + kk;
                const float* rp = kbase + kr * AROW;
                float p = 0.f;
#pragma unroll
                for (int bb = 0; bb < 4; bb++) {
                    float4 u0 = *(const float4*)(rp + fbo[bb]);
                    float4 u1 = *(const float4*)(rp + fbo[bb] + 4);
                    p = fmaf(qreg[bb * 8 + 0], u0.x, p);
                    p = fmaf(qreg[bb * 8 + 1], u0.y, p);
                    p = fmaf(qreg[bb * 8 + 2], u0.z, p);
                    p = fmaf(qreg[bb * 8 + 3], u0.w, p);
                    p = fmaf(qreg[bb * 8 + 4], u1.x, p);
                    p = fmaf(qreg[bb * 8 + 5], u1.y, p);
                    p = fmaf(qreg[bb * 8 + 6], u1.z, p);
                    p = fmaf(qreg[bb * 8 + 7], u1.w, p);
                }
                p += __shfl_xor_sync(0xffffffffu, p, 1);
                p += __shfl_xor_sync(0xffffffffu, p, 2);
                s[kk] = (full || (kt + kr <= qg)) ? p : -1e30f;
            }
            float mx = m;
#pragma unroll
            for (int kk = 0; kk < 16; kk++) mx = fmaxf(mx, s[kk]);
            float corr = __expf(m - mx);
            m = mx;
            l *= corr;
#pragma unroll
            for (int j = 0; j < 32; j++) acc[j] *= corr;
#pragma unroll
            for (int kk = 0; kk < 16; kk++) {
                float pw = __expf(s[kk] - mx);
                l += pw;
                const float* vr_ = vbase + (cch * 16 + kk) * AROW;
#pragma unroll
                for (int bb = 0; bb < 4; bb++) {
                    float4 w0 = *(const float4*)(vr_ + fbo[bb]);
                    float4 w1 = *(const float4*)(vr_ + fbo[bb] + 4);
                    acc[bb * 8 + 0] = fmaf(pw, w0.x, acc[bb * 8 + 0]);
                    acc[bb * 8 + 1] = fmaf(pw, w0.y, acc[bb * 8 + 1]);
                    acc[bb * 8 + 2] = fmaf(pw, w0.z, acc[bb * 8 + 2]);
                    acc[bb * 8 + 3] = fmaf(pw, w0.w, acc[bb * 8 + 3]);
                    acc[bb * 8 + 4] = fmaf(pw, w1.x, acc[bb * 8 + 4]);
                    acc[bb * 8 + 5] = fmaf(pw, w1.y, acc[bb * 8 + 5]);
                    acc[bb * 8 + 6] = fmaf(pw, w1.z, acc[bb * 8 + 6]);
                    acc[bb * 8 + 7] = fmaf(pw, w1.w, acc[bb * 8 + 7]);
                }
            }
        }
        __syncthreads();
    }

    const float inv = 1.f / l;
    uint32_t* op = O + ((size_t)(b * SEQ + qg)) * (NH * HD) + h * HD;
#pragma unroll
    for (int bb = 0; bb < 4; bb++) {
        uint4 o0, o1;
        o0.x = f2tf32(acc[bb * 8 + 0] * inv); o0.y = f2tf32(acc[bb * 8 + 1] * inv);
        o0.z = f2tf32(acc[bb * 8 + 2] * inv); o0.w = f2tf32(acc[bb * 8 + 3] * inv);
        o1.x = f2tf32(acc[bb * 8 + 4] * inv); o1.y = f2tf32(acc[bb * 8 + 5] * inv);
        o1.z = f2tf32(acc[bb * 8 + 6] * inv); o1.w = f2tf32(acc[bb * 8 + 7] * inv);
        *(uint4*)(op + fbo[bb])     = o0;
        *(uint4*)(op + fbo[bb] + 4) = o1;
    }
#undef LOAD_TILE
}

// ---------------------------------------------------------------------------
// Host launcher
// ---------------------------------------------------------------------------
extern "C" void kernel_launch(void* const* d_in, const int* in_sizes, int n_in,
                              void* d_out, int out_size)
{
    const float* hs   = (const float*)d_in[0];
    const float* cosp = (const float*)d_in[1];
    const float* sinp = (const float*)d_in[2];
    const float* Wq   = (const float*)d_in[3];
    const float* bq   = (const float*)d_in[4];
    const float* Wk   = (const float*)d_in[5];
    const float* bk   = (const float*)d_in[6];
    const float* Wv   = (const float*)d_in[7];
    const float* bv   = (const float*)d_in[8];
    const float* Wo   = (const float*)d_in[9];
    float* out = (float*)d_out;

    float *qp, *kp, *vp;
    uint32_t *ap, *hst, *wqt, *wkt, *wvt, *wot;
    cudaGetSymbolAddress((void**)&qp,  g_q);
    cudaGetSymbolAddress((void**)&kp,  g_k);
    cudaGetSymbolAddress((void**)&vp,  g_v);
    cudaGetSymbolAddress((void**)&ap,  g_att);
    cudaGetSymbolAddress((void**)&hst, g_hs_t);
    cudaGetSymbolAddress((void**)&wqt, g_wq_t);
    cudaGetSymbolAddress((void**)&wkt, g_wk_t);
    cudaGetSymbolAddress((void**)&wvt, g_wv_t);
    cudaGetSymbolAddress((void**)&wot, g_wo_t);

    cudaFuncSetAttribute(gemm_tf32_v2, cudaFuncAttributeMaxDynamicSharedMemorySize, GEMM_SMEM);
    cudaFuncSetAttribute(attn_kernel,  cudaFuncAttributeMaxDynamicSharedMemorySize, ATTN_SMEM);

    // Pre-round operands to tf32 bits
    const int CT = 256;
    cvt_tf32_kernel<<<(MROWS * HID / 4 + CT - 1) / CT, CT>>>(hs, hst, MROWS * HID);
    cvt_tf32_kernel<<<(NH * HD * HID / 4 + CT - 1) / CT, CT>>>(Wq, wqt, NH * HD * HID);
    cvt_tf32_kernel<<<(NKV * HD * HID / 4 + CT - 1) / CT, CT>>>(Wk, wkt, NKV * HD * HID);
    cvt_tf32_kernel<<<(NKV * HD * HID / 4 + CT - 1) / CT, CT>>>(Wv, wvt, NKV * HD * HID);
    cvt_tf32_kernel<<<(HID * NH * HD / 4 + CT - 1) / CT, CT>>>(Wo, wot, HID * NH * HD);

    // QKV projections
    gemm_tf32_v2<<<dim3(NH * HD / 128, MROWS / 128), 128, GEMM_SMEM>>>(
        hst, wqt, bq, qp, MROWS, NH * HD, HID);
    gemm_tf32_v2<<<dim3(NKV * HD / 128, MROWS / 128), 128, GEMM_SMEM>>>(
        hst, wkt, bk, kp, MROWS, NKV * HD, HID);
    gemm_tf32_v2<<<dim3(NKV * HD / 128, MROWS / 128), 128, GEMM_SMEM>>>(
        hst, wvt, bv, vp, MROWS, NKV * HD, HID);

    // RoPE on Q and K
    rope_kernel<<<(MROWS * NH * 64 + 255) / 256, 256>>>(qp, cosp, sinp, NH);
    rope_kernel<<<(MROWS * NKV * 64 + 255) / 256, 256>>>(kp, cosp, sinp, NKV);

    // Causal GQA attention (writes tf32 bits)
    attn_kernel<<<dim3(SEQ / AQ2, NH, BATCH), 512, ATTN_SMEM>>>(qp, kp, vp, ap);

    // Output projection
    gemm_tf32_v2<<<dim3(HID / 128, MROWS / 128), 128, GEMM_SMEM>>>(
        ap, wot, nullptr, out, MROWS, HID, HID);
}

// round 9
// speedup vs baseline: 6.3833x; 2.1434x over previous
#include <cuda_runtime.h>
#include <cuda_bf16.h>
#include <math.h>
#include <stdint.h>

// Problem constants
#define BATCH 2
#define SEQ   2048
#define HID   3584
#define NH    28
#define NKV   4
#define HD    128
#define GROUPS (NH / NKV)   // 7
#define MROWS (BATCH * SEQ) // 4096

// Scratch buffers (static device globals; no runtime allocation)
__device__ uint32_t g_q[MROWS * NH * HD];     // Q: fp32 from gemm, tf32 bits after rope
__device__ uint32_t g_k[MROWS * NKV * HD];    // K: fp32 from gemm, tf32 bits after rope
__device__ uint32_t g_v[MROWS * NKV * HD];    // V: fp32 from gemm, tf32 bits after cvt
__device__ uint32_t g_att[MROWS * NH * HD];   // attn out, tf32 bits
__device__ uint32_t g_hs_t[MROWS * HID];      // hidden_states, tf32 bits
__device__ uint32_t g_wq_t[NH * HD * HID];
__device__ uint32_t g_wk_t[NKV * HD * HID];
__device__ uint32_t g_wv_t[NKV * HD * HID];
__device__ uint32_t g_wo_t[HID * NH * HD];

// ---------------------------------------------------------------------------
// Helpers
// ---------------------------------------------------------------------------
__device__ __forceinline__ uint32_t f2tf32(float x) {
    uint32_t r;
    asm("cvt.rna.tf32.f32 %0, %1;" : "=r"(r) : "f"(x));
    return r;
}

__device__ __forceinline__ void mma_tf32(float* c, const uint32_t* a, const uint32_t* b) {
    asm volatile(
        "mma.sync.aligned.m16n8k8.row.col.f32.tf32.tf32.f32 "
        "{%0,%1,%2,%3}, {%4,%5,%6,%7}, {%8,%9}, {%0,%1,%2,%3};"
        : "+f"(c[0]), "+f"(c[1]), "+f"(c[2]), "+f"(c[3])
        : "r"(a[0]), "r"(a[1]), "r"(a[2]), "r"(a[3]), "r"(b[0]), "r"(b[1]));
}

__device__ __forceinline__ uint32_t smem_u32(const void* p) {
    return (uint32_t)__cvta_generic_to_shared(p);
}
__device__ __forceinline__ void cp_async16(uint32_t dst, const void* src) {
    asm volatile("cp.async.cg.shared.global [%0], [%1], 16;\n" :: "r"(dst), "l"(src));
}
#define CP_COMMIT() asm volatile("cp.async.commit_group;\n")
#define CP_WAIT1()  asm volatile("cp.async.wait_group 1;\n")

// ---------------------------------------------------------------------------
// Elementwise fp32 -> tf32 bits (out-of-place and in-place variants)
// ---------------------------------------------------------------------------
__global__ void cvt_tf32_kernel(const float* __restrict__ src,
                                uint32_t* __restrict__ dst, int n)
{
    int i = (blockIdx.x * blockDim.x + threadIdx.x) * 4;
    if (i >= n) return;
    float4 v = *(const float4*)(src + i);
    uint4 o;
    o.x = f2tf32(v.x); o.y = f2tf32(v.y); o.z = f2tf32(v.z); o.w = f2tf32(v.w);
    *(uint4*)(dst + i) = o;
}

__global__ void cvt_tf32_inplace_kernel(uint32_t* buf, int n)
{
    int i = (blockIdx.x * blockDim.x + threadIdx.x) * 4;
    if (i >= n) return;
    uint4 w = *(uint4*)(buf + i);
    uint4 o;
    o.x = f2tf32(__uint_as_float(w.x)); o.y = f2tf32(__uint_as_float(w.y));
    o.z = f2tf32(__uint_as_float(w.z)); o.w = f2tf32(__uint_as_float(w.w));
    *(uint4*)(buf + i) = o;
}

// ---------------------------------------------------------------------------
// TF32 GEMM v2: C[M,N] = A[M,K] @ B[N,K]^T (+bias). A,B are tf32 bits.
// 128x128 CTA, BK=16, 3-stage cp.async, 4 warps each 64x64 (m16n8k8 mma).
// ---------------------------------------------------------------------------
#define GSKP 20                      // smem word stride per row
#define GSTAGE_WORDS (128 * GSKP)    // 2560 words per operand per stage
#define GEMM_SMEM (3 * 2 * GSTAGE_WORDS * 4)  // 61440 bytes

__global__ void __launch_bounds__(128) gemm_tf32_v2(
    const uint32_t* __restrict__ A, const uint32_t* __restrict__ B,
    const float* __restrict__ bias, float* __restrict__ C,
    int M, int N, int K)
{
    extern __shared__ unsigned char dynsmem[];
    uint32_t* Asb = (uint32_t*)dynsmem;                   // [3][128][20]
    uint32_t* Bsb = Asb + 3 * GSTAGE_WORDS;               // [3][128][20]

    const int tid  = threadIdx.x;
    const int lane = tid & 31;
    const int warp = tid >> 5;
    const int wm   = warp & 1;   // m offset 0/64
    const int wn   = warp >> 1;  // n offset 0/64
    const int bm = blockIdx.y * 128;
    const int bn = blockIdx.x * 128;

    const uint32_t* Ap = A + (size_t)(bm + tid) * K;
    const uint32_t* Bp = B + (size_t)(bn + tid) * K;
    const uint32_t sA = smem_u32(Asb + tid * GSKP);
    const uint32_t sB = smem_u32(Bsb + tid * GSKP);

    float acc[4][8][4];
#pragma unroll
    for (int mi = 0; mi < 4; mi++)
#pragma unroll
        for (int ni = 0; ni < 8; ni++)
#pragma unroll
            for (int r = 0; r < 4; r++) acc[mi][ni][r] = 0.f;

    const int ktiles = K / 16;

#define LOAD_STAGE(s, k0) do {                                         \
        uint32_t da = sA + (s) * (GSTAGE_WORDS * 4);                   \
        uint32_t db = sB + (s) * (GSTAGE_WORDS * 4);                   \
        _Pragma("unroll")                                              \
        for (int c = 0; c < 4; c++) {                                  \
            cp_async16(da + c * 16, Ap + (k0) + c * 4);                \
            cp_async16(db + c * 16, Bp + (k0) + c * 4);                \
        }                                                              \
    } while (0)

    LOAD_STAGE(0, 0);  CP_COMMIT();
    LOAD_STAGE(1, 16); CP_COMMIT();

    int s_load = 2;
    int s_cur  = 0;
    for (int t = 0; t < ktiles; t++) {
        CP_WAIT1();
        __syncthreads();
        if (t + 2 < ktiles) LOAD_STAGE(s_load, (t + 2) * 16);
        CP_COMMIT();
        if (++s_load == 3) s_load = 0;

        const uint32_t* As_ = Asb + s_cur * GSTAGE_WORDS;
        const uint32_t* Bs_ = Bsb + s_cur * GSTAGE_WORDS;
        if (++s_cur == 3) s_cur = 0;

#pragma unroll
        for (int ks = 0; ks < 2; ks++) {
            const int kc = ks * 8 + (lane & 3);
            uint32_t af[4][4];
#pragma unroll
            for (int mi = 0; mi < 4; mi++) {
                int r = wm * 64 + mi * 16 + (lane >> 2);
                af[mi][0] = As_[r * GSKP + kc];
                af[mi][1] = As_[(r + 8) * GSKP + kc];
                af[mi][2] = As_[r * GSKP + kc + 4];
                af[mi][3] = As_[(r + 8) * GSKP + kc + 4];
            }
            uint32_t bf[8][2];
#pragma unroll
            for (int ni = 0; ni < 8; ni++) {
                int n = wn * 64 + ni * 8 + (lane >> 2);
                bf[ni][0] = Bs_[n * GSKP + kc];
                bf[ni][1] = Bs_[n * GSKP + kc + 4];
            }
#pragma unroll
            for (int mi = 0; mi < 4; mi++)
#pragma unroll
                for (int ni = 0; ni < 8; ni++)
                    mma_tf32(acc[mi][ni], af[mi], bf[ni]);
        }
    }

#pragma unroll
    for (int mi = 0; mi < 4; mi++) {
        int r = bm + wm * 64 + mi * 16 + (lane >> 2);
#pragma unroll
        for (int ni = 0; ni < 8; ni++) {
            int c = bn + wn * 64 + ni * 8 + (lane & 3) * 2;
            float b0 = bias ? bias[c]     : 0.f;
            float b1 = bias ? bias[c + 1] : 0.f;
            float2 v0 = make_float2(acc[mi][ni][0] + b0, acc[mi][ni][1] + b1);
            float2 v1 = make_float2(acc[mi][ni][2] + b0, acc[mi][ni][3] + b1);
            *(float2*)&C[(size_t)r * N + c]       = v0;
            *(float2*)&C[(size_t)(r + 8) * N + c] = v1;
        }
    }
#undef LOAD_STAGE
}

// ---------------------------------------------------------------------------
// RoPE: reads fp32, writes TF32 BITS in place. x[M, nheads*128].
// ---------------------------------------------------------------------------
__global__ void rope_kernel(uint32_t* __restrict__ x,
                            const float* __restrict__ cosp,
                            const float* __restrict__ sinp,
                            int nheads)
{
    int idx = blockIdx.x * blockDim.x + threadIdx.x;
    int total = MROWS * nheads * 64;
    if (idx >= total) return;
    int d = idx & 63;
    int t = idx >> 6;
    int hd = t % nheads;
    int row = t / nheads;

    uint32_t* p = x + (size_t)row * nheads * HD + hd * HD;
    const float* cr = cosp + (size_t)row * HD;
    const float* sr = sinp + (size_t)row * HD;

    float x1 = __uint_as_float(p[d]), x2 = __uint_as_float(p[d + 64]);
    float c1 = cr[d], c2 = cr[d + 64];
    float s1 = sr[d], s2 = sr[d + 64];
    p[d]      = f2tf32(x1 * c1 - x2 * s1);
    p[d + 64] = f2tf32(x2 * c2 + x1 * s2);
}

// ---------------------------------------------------------------------------
// Causal GQA flash attention v3: tensor-core mma for S=QK^T and O=PV.
// 256 threads = 8 warps; each warp owns 16 q-rows (128 q-rows/CTA).
// K tiles of 64 keys, double-buffered cp.async. All operands tf32 bits.
// fp32 accumulation, online softmax on raw scores (scale folded into exp).
// ---------------------------------------------------------------------------
#define KSTR 132                       // padded words per smem row
#define KVW  (64 * KSTR)               // 8448 words per operand per stage
#define ATTN_SMEM (4 * KVW * 4)        // K[2] + V[2] = 135168 bytes

__global__ void __launch_bounds__(256) attn_mma(
    const uint32_t* __restrict__ Q, const uint32_t* __restrict__ Kg,
    const uint32_t* __restrict__ Vg, uint32_t* __restrict__ O)
{
    extern __shared__ unsigned char dynsmem[];
    uint32_t* Ksm = (uint32_t*)dynsmem;      // [2][64][132]
    uint32_t* Vsm = Ksm + 2 * KVW;           // [2][64][132]

    const int tid  = threadIdx.x;
    const int lane = tid & 31;
    const int warp = tid >> 5;
    const int q0   = (gridDim.x - 1 - (int)blockIdx.x) * 128;  // heavy blocks first
    const int h    = blockIdx.y;
    const int b    = blockIdx.z;
    const int kvh  = h / GROUPS;
    const float scale = 0.08838834764831845f; // 1/sqrt(128)

    const int r0 = q0 + warp * 16 + (lane >> 2);   // rows r0 and r0+8

    // Q fragments (tf32 bits) straight from gmem, kept for the whole block
    uint32_t qf[16][4];
    {
        const uint32_t* qb = Q + (size_t)(b * SEQ) * (NH * HD) + h * HD;
        const size_t st = (size_t)(NH * HD);
#pragma unroll
        for (int k16 = 0; k16 < 16; k16++) {
            int c = k16 * 8 + (lane & 3);
            qf[k16][0] = qb[(size_t)r0 * st + c];
            qf[k16][1] = qb[(size_t)(r0 + 8) * st + c];
            qf[k16][2] = qb[(size_t)r0 * st + c + 4];
            qf[k16][3] = qb[(size_t)(r0 + 8) * st + c + 4];
        }
    }

    float of[16][4];
#pragma unroll
    for (int d = 0; d < 16; d++)
#pragma unroll
        for (int c = 0; c < 4; c++) of[d][c] = 0.f;
    float m0 = -1e30f, m1 = -1e30f, l0 = 0.f, l1 = 0.f;

#define LOAD_KV(st_, kt_) do {                                                  \
        _Pragma("unroll")                                                       \
        for (int i = 0; i < 8; i++) {                                           \
            int cid = tid + i * 256;                                            \
            int r   = cid >> 5;                                                 \
            int c4  = (cid & 31) * 4;                                           \
            size_t g = ((size_t)(b * SEQ + (kt_) + r)) * (NKV * HD)             \
                       + kvh * HD + c4;                                         \
            cp_async16(smem_u32(Ksm + (st_) * KVW + r * KSTR + c4), Kg + g);    \
            cp_async16(smem_u32(Vsm + (st_) * KVW + r * KSTR + c4), Vg + g);    \
        }                                                                       \
    } while (0)

    const int ntiles = q0 / 64 + 2;
    LOAD_KV(0, 0);
    CP_COMMIT();

    for (int t = 0; t < ntiles; t++) {
        if (t + 1 < ntiles) LOAD_KV((t + 1) & 1, (t + 1) * 64);
        CP_COMMIT();
        CP_WAIT1();
        __syncthreads();

        const uint32_t* kb_ = Ksm + (t & 1) * KVW;
        const uint32_t* vb_ = Vsm + (t & 1) * KVW;
        const int kt = t * 64;

        // ---- S = Q K^T over this 64-key tile ----
        float s[8][4];
#pragma unroll
        for (int j = 0; j < 8; j++)
#pragma unroll
            for (int c = 0; c < 4; c++) s[j][c] = 0.f;

#pragma unroll
        for (int k16 = 0; k16 < 16; k16++) {
            const int kc = k16 * 8 + (lane & 3);
            uint32_t bb[8][2];
#pragma unroll
            for (int j = 0; j < 8; j++) {
                int key = j * 8 + (lane >> 2);
                bb[j][0] = kb_[key * KSTR + kc];
                bb[j][1] = kb_[key * KSTR + kc + 4];
            }
#pragma unroll
            for (int j = 0; j < 8; j++)
                mma_tf32(s[j], qf[k16], bb[j]);
        }

        // ---- causal mask (only near-diagonal tiles) ----
        if (kt + 63 > q0 + warp * 16) {
#pragma unroll
            for (int j = 0; j < 8; j++) {
                int colb = kt + j * 8 + (lane & 3) * 2;
                if (colb > r0)     s[j][0] = -1e30f;
                if (colb + 1 > r0) s[j][1] = -1e30f;
                if (colb > r0 + 8)     s[j][2] = -1e30f;
                if (colb + 1 > r0 + 8) s[j][3] = -1e30f;
            }
        }

        // ---- online softmax (raw-score max; scale folded into exp) ----
        float mx0 = -1e30f, mx1 = -1e30f;
#pragma unroll
        for (int j = 0; j < 8; j++) {
            mx0 = fmaxf(mx0, fmaxf(s[j][0], s[j][1]));
            mx1 = fmaxf(mx1, fmaxf(s[j][2], s[j][3]));
        }
        mx0 = fmaxf(mx0, __shfl_xor_sync(0xffffffffu, mx0, 1));
        mx0 = fmaxf(mx0, __shfl_xor_sync(0xffffffffu, mx0, 2));
        mx1 = fmaxf(mx1, __shfl_xor_sync(0xffffffffu, mx1, 1));
        mx1 = fmaxf(mx1, __shfl_xor_sync(0xffffffffu, mx1, 2));
        float nm0 = fmaxf(m0, mx0), nm1 = fmaxf(m1, mx1);
        float corr0 = __expf((m0 - nm0) * scale);
        float corr1 = __expf((m1 - nm1) * scale);
        m0 = nm0; m1 = nm1;

        float ps0 = 0.f, ps1 = 0.f;
#pragma unroll
        for (int j = 0; j < 8; j++) {
            s[j][0] = __expf((s[j][0] - m0) * scale); ps0 += s[j][0];
            s[j][1] = __expf((s[j][1] - m0) * scale); ps0 += s[j][1];
            s[j][2] = __expf((s[j][2] - m1) * scale); ps1 += s[j][2];
            s[j][3] = __expf((s[j][3] - m1) * scale); ps1 += s[j][3];
        }
        ps0 += __shfl_xor_sync(0xffffffffu, ps0, 1);
        ps0 += __shfl_xor_sync(0xffffffffu, ps0, 2);
        ps1 += __shfl_xor_sync(0xffffffffu, ps1, 1);
        ps1 += __shfl_xor_sync(0xffffffffu, ps1, 2);
        l0 = l0 * corr0 + ps0;
        l1 = l1 * corr1 + ps1;
#pragma unroll
        for (int d = 0; d < 16; d++) {
            of[d][0] *= corr0; of[d][1] *= corr0;
            of[d][2] *= corr1; of[d][3] *= corr1;
        }

        // ---- O += P V : build P A-frags by shuffle, V B-frags from smem ----
        const int src1 = (lane & ~3) | ((lane & 3) >> 1);
        const int src2 = src1 + 2;
#pragma unroll
        for (int j = 0; j < 8; j++) {
            uint32_t w0 = f2tf32(s[j][0]);
            uint32_t w1 = f2tf32(s[j][1]);
            uint32_t w2 = f2tf32(s[j][2]);
            uint32_t w3 = f2tf32(s[j][3]);
            uint32_t t00 = __shfl_sync(0xffffffffu, w0, src1);
            uint32_t t01 = __shfl_sync(0xffffffffu, w1, src1);
            uint32_t t10 = __shfl_sync(0xffffffffu, w2, src1);
            uint32_t t11 = __shfl_sync(0xffffffffu, w3, src1);
            uint32_t u00 = __shfl_sync(0xffffffffu, w0, src2);
            uint32_t u01 = __shfl_sync(0xffffffffu, w1, src2);
            uint32_t u10 = __shfl_sync(0xffffffffu, w2, src2);
            uint32_t u11 = __shfl_sync(0xffffffffu, w3, src2);
            uint32_t pa[4];
            pa[0] = (lane & 1) ? t01 : t00;
            pa[1] = (lane & 1) ? t11 : t10;
            pa[2] = (lane & 1) ? u01 : u00;
            pa[3] = (lane & 1) ? u11 : u10;

            const int key0 = j * 8 + (lane & 3);
            const int dn   = (lane >> 2);
#pragma unroll
            for (int d = 0; d < 16; d++) {
                uint32_t vb[2];
                vb[0] = vb_[key0 * KSTR + d * 8 + dn];
                vb[1] = vb_[(key0 + 4) * KSTR + d * 8 + dn];
                mma_tf32(of[d], pa, vb);
            }
        }
        __syncthreads();
    }

    // ---- epilogue: normalize, write tf32 bits ----
    const float inv0 = 1.f / l0;
    const float inv1 = 1.f / l1;
    uint32_t* op0 = O + (size_t)(b * SEQ + r0) * (NH * HD) + h * HD;
    uint32_t* op1 = op0 + (size_t)8 * (NH * HD);
#pragma unroll
    for (int d = 0; d < 16; d++) {
        int c = d * 8 + (lane & 3) * 2;
        uint2 v0, v1;
        v0.x = f2tf32(of[d][0] * inv0); v0.y = f2tf32(of[d][1] * inv0);
        v1.x = f2tf32(of[d][2] * inv1); v1.y = f2tf32(of[d][3] * inv1);
        *(uint2*)(op0 + c) = v0;
        *(uint2*)(op1 + c) = v1;
    }
#undef LOAD_KV
}

// ---------------------------------------------------------------------------
// Host launcher
// ---------------------------------------------------------------------------
extern "C" void kernel_launch(void* const* d_in, const int* in_sizes, int n_in,
                              void* d_out, int out_size)
{
    const float* hs   = (const float*)d_in[0];
    const float* cosp = (const float*)d_in[1];
    const float* sinp = (const float*)d_in[2];
    const float* Wq   = (const float*)d_in[3];
    const float* bq   = (const float*)d_in[4];
    const float* Wk   = (const float*)d_in[5];
    const float* bk   = (const float*)d_in[6];
    const float* Wv   = (const float*)d_in[7];
    const float* bv   = (const float*)d_in[8];
    const float* Wo   = (const float*)d_in[9];
    float* out = (float*)d_out;

    uint32_t *qp, *kp, *vp, *ap, *hst, *wqt, *wkt, *wvt, *wot;
    cudaGetSymbolAddress((void**)&qp,  g_q);
    cudaGetSymbolAddress((void**)&kp,  g_k);
    cudaGetSymbolAddress((void**)&vp,  g_v);
    cudaGetSymbolAddress((void**)&ap,  g_att);
    cudaGetSymbolAddress((void**)&hst, g_hs_t);
    cudaGetSymbolAddress((void**)&wqt, g_wq_t);
    cudaGetSymbolAddress((void**)&wkt, g_wk_t);
    cudaGetSymbolAddress((void**)&wvt, g_wv_t);
    cudaGetSymbolAddress((void**)&wot, g_wo_t);

    cudaFuncSetAttribute(gemm_tf32_v2, cudaFuncAttributeMaxDynamicSharedMemorySize, GEMM_SMEM);
    cudaFuncSetAttribute(attn_mma,     cudaFuncAttributeMaxDynamicSharedMemorySize, ATTN_SMEM);

    // Pre-round GEMM operands to tf32 bits
    const int CT = 256;
    cvt_tf32_kernel<<<(MROWS * HID / 4 + CT - 1) / CT, CT>>>(hs, hst, MROWS * HID);
    cvt_tf32_kernel<<<(NH * HD * HID / 4 + CT - 1) / CT, CT>>>(Wq, wqt, NH * HD * HID);
    cvt_tf32_kernel<<<(NKV * HD * HID / 4 + CT - 1) / CT, CT>>>(Wk, wkt, NKV * HD * HID);
    cvt_tf32_kernel<<<(NKV * HD * HID / 4 + CT - 1) / CT, CT>>>(Wv, wvt, NKV * HD * HID);
    cvt_tf32_kernel<<<(HID * NH * HD / 4 + CT - 1) / CT, CT>>>(Wo, wot, HID * NH * HD);

    // QKV projections (write fp32)
    gemm_tf32_v2<<<dim3(NH * HD / 128, MROWS / 128), 128, GEMM_SMEM>>>(
        hst, wqt, bq, (float*)qp, MROWS, NH * HD, HID);
    gemm_tf32_v2<<<dim3(NKV * HD / 128, MROWS / 128), 128, GEMM_SMEM>>>(
        hst, wkt, bk, (float*)kp, MROWS, NKV * HD, HID);
    gemm_tf32_v2<<<dim3(NKV * HD / 128, MROWS / 128), 128, GEMM_SMEM>>>(
        hst, wvt, bv, (float*)vp, MROWS, NKV * HD, HID);

    // RoPE on Q and K (fp32 in, tf32 bits out, in place); V -> tf32 bits
    rope_kernel<<<(MROWS * NH * 64 + 255) / 256, 256>>>(qp, cosp, sinp, NH);
    rope_kernel<<<(MROWS * NKV * 64 + 255) / 256, 256>>>(kp, cosp, sinp, NKV);
    cvt_tf32_inplace_kernel<<<(MROWS * NKV * HD / 4 + CT - 1) / CT, CT>>>(vp, MROWS * NKV * HD);

    // Causal GQA attention on tensor cores (tf32 bits in/out)
    attn_mma<<<dim3(SEQ / 128, NH, BATCH), 256, ATTN_SMEM>>>(qp, kp, vp, ap);

    // Output projection
    gemm_tf32_v2<<<dim3(HID / 128, MROWS / 128), 128, GEMM_SMEM>>>(
        ap, wot, nullptr, out, MROWS, HID, HID);
}